// round 8
// baseline (speedup 1.0000x reference)
#include <cuda_runtime.h>
#include <cuda_bf16.h>

// Problem constants (fixed shapes from reference setup_inputs)
#define BB 4
#define NN 16384
#define PP 1024
#define CC 128
#define NS 64
#define R2 0.04f

#define NTBLK (BB * 512 * 4)  // 8192 transpose blocks (scheduled FIRST)
#define NQBLK (BB * PP / 4)   // 1024 query blocks (scheduled LAST)

// Scratch (allocations forbidden; __device__ globals)
__device__ float g_ftrans[(size_t)BB * NN * CC];   // (B, N, C), 32 MB
__device__ int   g_idx[BB * PP * NS];              // masked gather indices

// Swizzled tile address: 64 s-rows x 64 channels, 16B-group XOR swizzle.
__device__ __forceinline__ int taddr(int s, int ch) {
    return s * 64 + (((ch >> 2) ^ (s & 15)) << 2) + (ch & 3);
}

// ---------------------------------------------------------------------------
// Kernel 1 (union grid): blocks [0, NTBLK) = transpose (short, DRAM-bound),
// blocks [NTBLK, NTBLK+NQBLK) = ball query (long, issue-bound). Scheduling
// transpose first lets query blocks backfill and co-run with transpose waves.
// ---------------------------------------------------------------------------
__global__ void __launch_bounds__(256) prep_kernel(
    const float* __restrict__ f, const float* __restrict__ xyz,
    const float* __restrict__ new_xyz, float* __restrict__ out) {
    const int bi = blockIdx.x;
    const int t = threadIdx.x;
    if (bi >= NTBLK) {
        // -------- ball query: 4 centers per block, shared scan --------
        __shared__ int sidx[4][NS];
        __shared__ unsigned long long wcA[2][8], wcB[2][8];
        const int warp = t >> 5;
        const int lane = t & 31;
        const int pb0 = (bi - NTBLK) * 4;    // first center id (same batch)
        const int b = pb0 >> 10;
        const float* xb = xyz + (size_t)b * NN * 3;

        float qx[4], qy[4], qz[4];
#pragma unroll
        for (int g = 0; g < 4; g++) {
            qx[g] = new_xyz[(size_t)(pb0 + g) * 3 + 0];
            qy[g] = new_xyz[(size_t)(pb0 + g) * 3 + 1];
            qz[g] = new_xyz[(size_t)(pb0 + g) * 3 + 2];
        }

        // prefetch chunk 0: thread owns points t and t+256
        float x0 = xb[t * 3 + 0], y0 = xb[t * 3 + 1], z0 = xb[t * 3 + 2];
        float x1 = xb[(t + 256) * 3 + 0], y1 = xb[(t + 256) * 3 + 1],
              z1 = xb[(t + 256) * 3 + 2];

        int cnt[4] = {0, 0, 0, 0};
        int sel = 0;
        const unsigned lm = (1u << lane) - 1u;
        for (int base = 0; base < NN; base += 512) {
            unsigned m0[4], m1[4];
            bool h0[4], h1[4];
#pragma unroll
            for (int g = 0; g < 4; g++) {
                // JAX f32 rounding: no FMA contraction, left-to-right sum.
                const float ax = __fadd_rn(qx[g], -x0), ay = __fadd_rn(qy[g], -y0),
                            az = __fadd_rn(qz[g], -z0);
                const float d0 = __fadd_rn(
                    __fadd_rn(__fmul_rn(ax, ax), __fmul_rn(ay, ay)),
                    __fmul_rn(az, az));
                const float bx = __fadd_rn(qx[g], -x1), by = __fadd_rn(qy[g], -y1),
                            bz = __fadd_rn(qz[g], -z1);
                const float d1 = __fadd_rn(
                    __fadd_rn(__fmul_rn(bx, bx), __fmul_rn(by, by)),
                    __fmul_rn(bz, bz));
                h0[g] = d0 < R2;
                h1[g] = d1 < R2;
                m0[g] = __ballot_sync(0xffffffffu, h0[g]);
                m1[g] = __ballot_sync(0xffffffffu, h1[g]);
            }
            if (lane == 0) {
                wcA[sel][warp] =
                    (unsigned long long)__popc(m0[0]) |
                    ((unsigned long long)__popc(m1[0]) << 16) |
                    ((unsigned long long)__popc(m0[1]) << 32) |
                    ((unsigned long long)__popc(m1[1]) << 48);
                wcB[sel][warp] =
                    (unsigned long long)__popc(m0[2]) |
                    ((unsigned long long)__popc(m1[2]) << 16) |
                    ((unsigned long long)__popc(m0[3]) << 32) |
                    ((unsigned long long)__popc(m1[3]) << 48);
            }
            // prefetch next chunk BEFORE the barrier
            const int nb = base + 512;
            if (nb < NN) {
                x0 = xb[(nb + t) * 3 + 0];
                y0 = xb[(nb + t) * 3 + 1];
                z0 = xb[(nb + t) * 3 + 2];
                x1 = xb[(nb + 256 + t) * 3 + 0];
                y1 = xb[(nb + 256 + t) * 3 + 1];
                z1 = xb[(nb + 256 + t) * 3 + 2];
            }
            __syncthreads();   // the ONLY barrier per iteration

            unsigned long long preA = 0, totA = 0, preB = 0, totB = 0;
#pragma unroll
            for (int w = 0; w < 8; w++) {
                const unsigned long long va = wcA[sel][w], vb = wcB[sel][w];
                if (w < warp) { preA += va; preB += vb; }
                totA += va; totB += vb;
            }
#pragma unroll
            for (int g = 0; g < 4; g++) {
                const unsigned long long pre = (g < 2) ? preA : preB;
                const unsigned long long tot = (g < 2) ? totA : totB;
                const int sh = (g & 1) * 32;
                const int p0 = (int)((pre >> sh) & 0xffff);
                const int p1 = (int)((pre >> (sh + 16)) & 0xffff);
                const int t0 = (int)((tot >> sh) & 0xffff);
                const int t1 = (int)((tot >> (sh + 16)) & 0xffff);
                const int pos0 = cnt[g] + p0 + __popc(m0[g] & lm);
                if (h0[g] && pos0 < NS) sidx[g][pos0] = base + t;
                const int pos1 = cnt[g] + t0 + p1 + __popc(m1[g] & lm);
                if (h1[g] && pos1 < NS) sidx[g][pos1] = base + 256 + t;
                cnt[g] += t0 + t1;   // uniform across block
            }
            sel ^= 1;
            if (cnt[0] >= NS && cnt[1] >= NS && cnt[2] >= NS && cnt[3] >= NS)
                break;
        }
        __syncthreads();       // sidx visible to all warps

        // ---- outputs: thread t handles center g = t>>6, slot s = t&63 ----
        {
            const int g = t >> 6;
            const int s = t & 63;
            const int p = (pb0 & 1023) + g;
            const int cn = cnt[g] < NS ? cnt[g] : NS;
            const int first = (cn > 0) ? sidx[g][0] : NN;
            const bool real = (s < cn);
            const int v = real ? sidx[g][s] : NN;
            const size_t o = (size_t)(pb0 + g) * NS;
            g_idx[o + s] = v;   // masked (pad -> NN)
            float* out_idx =
                out + (size_t)BB * 131 * PP * NS + (size_t)BB * 3 * PP * NS;
            out_idx[o + s] = (float)(real ? v : first);   // idx0 (pad -> first)

            // grouped_xyz + xyz_feature channels
            const float qgx = (g == 0) ? qx[0] : (g == 1) ? qx[1]
                              : (g == 2) ? qx[2] : qx[3];
            const float qgy = (g == 0) ? qy[0] : (g == 1) ? qy[1]
                              : (g == 2) ? qy[2] : qy[3];
            const float qgz = (g == 0) ? qz[0] : (g == 1) ? qz[1]
                              : (g == 2) ? qz[2] : qz[3];
            float* gx = out + (size_t)BB * 131 * PP * NS;
#pragma unroll
            for (int c = 0; c < 3; c++) {
                const float q = (c == 0) ? qgx : (c == 1) ? qgy : qgz;
                const float src = (v < NN) ? xb[v * 3 + c] : 1000000.0f;
                const float gv = __fadd_rn(src, -q);
                gx[(((size_t)b * 3 + c) * PP + p) * NS + s] = gv;
                const float xf = (gv > 100000.0f) ? 0.0f : gv;
                out[(((size_t)b * 131 + c) * PP + p) * NS + s] = xf / 0.2f;
            }
        }
    } else {
        // ---------------- transpose (B,C,N) -> (B,N,C) ----------------
        __shared__ float tile[32][33];
        const int b = bi >> 11;           // 2048 blocks per batch
        const int rem = bi & 2047;
        const int nBase = (rem >> 2) * 32;
        const int cBase = (rem & 3) * 32;
        const float* fb = f + (size_t)b * CC * NN;
        float* ob = g_ftrans + (size_t)b * NN * CC;
        const int tx = t & 31, ty = t >> 5;  // 32 x 8
#pragma unroll
        for (int i = 0; i < 32; i += 8)
            tile[ty + i][tx] = fb[(size_t)(cBase + ty + i) * NN + nBase + tx];
        __syncthreads();
#pragma unroll
        for (int i = 0; i < 32; i += 8)
            ob[(size_t)(nBase + ty + i) * CC + cBase + tx] = tile[tx][ty + i];
    }
}

// ---------------------------------------------------------------------------
// Kernel 2: feature gather. Block per (chunk-of-64-channels, p, b).
// LDG.128 gather -> STS.128 swizzled [s][ch] tile -> LDS + STG.128 output.
// ---------------------------------------------------------------------------
__global__ void __launch_bounds__(256, 8) gather_kernel(float* __restrict__ out) {
    __shared__ float ftile[64 * 64];    // 16 KB, swizzled
    __shared__ int smidx[NS];

    const int chunk = blockIdx.x;       // 0 / 1
    const int p = blockIdx.y;
    const int b = blockIdx.z;
    const int t = threadIdx.x;
    const int warp = t >> 5;
    const int lane = t & 31;

    if (t < NS) smidx[t] = g_idx[((size_t)b * PP + p) * NS + t];
    __syncthreads();

    // Phase A: gather. Warp handles 2 s-rows per iter (16 lanes x float4 each).
    const float* fb = g_ftrans + (size_t)b * NN * CC + chunk * 64;
    const int c4 = lane & 15;           // 16B group within the row
#pragma unroll
    for (int i = 0; i < 4; i++) {
        const int row = warp * 8 + i * 2 + (lane >> 4);
        const int n = smidx[row];
        float4 v = make_float4(0.f, 0.f, 0.f, 0.f);
        if (n < NN) v = *(const float4*)&fb[(size_t)n * CC + c4 * 4];
        *(float4*)&ftile[row * 64 + ((c4 ^ (row & 15)) << 2)] = v;
    }
    __syncthreads();

    // Phase B: write 64 channels x 64 s, STG.128 along s.
    float* nfb = out + (((size_t)b * 131 + 3 + chunk * 64) * PP + p) * NS;
    const int ch = t >> 2;              // 0..63 (within chunk)
#pragma unroll
    for (int k = 0; k < 4; k++) {
        const int sg = (t & 3) + 4 * k; // 0..15 (group of 4 s)
        float4 v;
        v.x = ftile[taddr(4 * sg + 0, ch)];
        v.y = ftile[taddr(4 * sg + 1, ch)];
        v.z = ftile[taddr(4 * sg + 2, ch)];
        v.w = ftile[taddr(4 * sg + 3, ch)];
        *(float4*)&nfb[(size_t)ch * PP * NS + sg * 4] = v;
    }
}

// ---------------------------------------------------------------------------
extern "C" void kernel_launch(void* const* d_in, const int* in_sizes, int n_in,
                              void* d_out, int out_size) {
    const float* xyz      = (const float*)d_in[0];  // (B, N, 3)
    const float* new_xyz  = (const float*)d_in[1];  // (B, P, 3)
    const float* features = (const float*)d_in[2];  // (B, C, N)
    float* out = (float*)d_out;

    prep_kernel<<<NTBLK + NQBLK, 256>>>(features, xyz, new_xyz, out);
    gather_kernel<<<dim3(2, PP, BB), 256>>>(out);
}

// round 9
// speedup vs baseline: 1.1868x; 1.1868x over previous
#include <cuda_runtime.h>
#include <cuda_bf16.h>

// Problem constants (fixed shapes from reference setup_inputs)
#define BB 4
#define NN 16384
#define PP 1024
#define CC 128
#define NS 64
#define R2 0.04f

// Scratch (allocations forbidden; __device__ globals)
__device__ float g_ftrans[(size_t)BB * NN * CC];   // (B, N, C), 32 MB
__device__ int   g_idx[BB * PP * NS];              // masked gather indices

// Swizzled tile address: 64 s-rows x 64 channels, 16B-group XOR swizzle.
__device__ __forceinline__ int taddr(int s, int ch) {
    return s * 64 + (((ch >> 2) ^ (s & 15)) << 2) + (ch & 3);
}

// ---------------------------------------------------------------------------
// Ball query for 4 consecutive centers (one block), shared xyz scan, SIMD-u64
// prefix, 1 barrier/iter, prefetched loads. Writes g_idx + idx0 + grouped_xyz
// + xyz_feature outputs. Proven bit-exact vs reference (rel_err 0.0).
// ---------------------------------------------------------------------------
__device__ __forceinline__ void ball_query_4(
    const int pb0, const float* __restrict__ xyz,
    const float* __restrict__ new_xyz, float* __restrict__ out) {
    __shared__ int sidx[4][NS];
    __shared__ unsigned long long wcA[2][8], wcB[2][8];
    const int t = threadIdx.x;
    const int warp = t >> 5;
    const int lane = t & 31;
    const int b = pb0 >> 10;
    const float* xb = xyz + (size_t)b * NN * 3;

    float qx[4], qy[4], qz[4];
#pragma unroll
    for (int g = 0; g < 4; g++) {
        qx[g] = new_xyz[(size_t)(pb0 + g) * 3 + 0];
        qy[g] = new_xyz[(size_t)(pb0 + g) * 3 + 1];
        qz[g] = new_xyz[(size_t)(pb0 + g) * 3 + 2];
    }

    // prefetch chunk 0: thread owns points t and t+256
    float x0 = xb[t * 3 + 0], y0 = xb[t * 3 + 1], z0 = xb[t * 3 + 2];
    float x1 = xb[(t + 256) * 3 + 0], y1 = xb[(t + 256) * 3 + 1],
          z1 = xb[(t + 256) * 3 + 2];

    int cnt[4] = {0, 0, 0, 0};
    int sel = 0;
    const unsigned lm = (1u << lane) - 1u;
    for (int base = 0; base < NN; base += 512) {
        unsigned m0[4], m1[4];
        bool h0[4], h1[4];
#pragma unroll
        for (int g = 0; g < 4; g++) {
            // JAX f32 rounding: no FMA contraction, left-to-right sum.
            const float ax = __fadd_rn(qx[g], -x0), ay = __fadd_rn(qy[g], -y0),
                        az = __fadd_rn(qz[g], -z0);
            const float d0 = __fadd_rn(
                __fadd_rn(__fmul_rn(ax, ax), __fmul_rn(ay, ay)),
                __fmul_rn(az, az));
            const float bx = __fadd_rn(qx[g], -x1), by = __fadd_rn(qy[g], -y1),
                        bz = __fadd_rn(qz[g], -z1);
            const float d1 = __fadd_rn(
                __fadd_rn(__fmul_rn(bx, bx), __fmul_rn(by, by)),
                __fmul_rn(bz, bz));
            h0[g] = d0 < R2;
            h1[g] = d1 < R2;
            m0[g] = __ballot_sync(0xffffffffu, h0[g]);
            m1[g] = __ballot_sync(0xffffffffu, h1[g]);
        }
        if (lane == 0) {
            wcA[sel][warp] =
                (unsigned long long)__popc(m0[0]) |
                ((unsigned long long)__popc(m1[0]) << 16) |
                ((unsigned long long)__popc(m0[1]) << 32) |
                ((unsigned long long)__popc(m1[1]) << 48);
            wcB[sel][warp] =
                (unsigned long long)__popc(m0[2]) |
                ((unsigned long long)__popc(m1[2]) << 16) |
                ((unsigned long long)__popc(m0[3]) << 32) |
                ((unsigned long long)__popc(m1[3]) << 48);
        }
        // prefetch next chunk BEFORE the barrier
        const int nb = base + 512;
        if (nb < NN) {
            x0 = xb[(nb + t) * 3 + 0];
            y0 = xb[(nb + t) * 3 + 1];
            z0 = xb[(nb + t) * 3 + 2];
            x1 = xb[(nb + 256 + t) * 3 + 0];
            y1 = xb[(nb + 256 + t) * 3 + 1];
            z1 = xb[(nb + 256 + t) * 3 + 2];
        }
        __syncthreads();   // the ONLY barrier per iteration

        unsigned long long preA = 0, totA = 0, preB = 0, totB = 0;
#pragma unroll
        for (int w = 0; w < 8; w++) {
            const unsigned long long va = wcA[sel][w], vb = wcB[sel][w];
            if (w < warp) { preA += va; preB += vb; }
            totA += va; totB += vb;
        }
#pragma unroll
        for (int g = 0; g < 4; g++) {
            const unsigned long long pre = (g < 2) ? preA : preB;
            const unsigned long long tot = (g < 2) ? totA : totB;
            const int sh = (g & 1) * 32;
            const int p0 = (int)((pre >> sh) & 0xffff);
            const int p1 = (int)((pre >> (sh + 16)) & 0xffff);
            const int t0 = (int)((tot >> sh) & 0xffff);
            const int t1 = (int)((tot >> (sh + 16)) & 0xffff);
            const int pos0 = cnt[g] + p0 + __popc(m0[g] & lm);
            if (h0[g] && pos0 < NS) sidx[g][pos0] = base + t;
            const int pos1 = cnt[g] + t0 + p1 + __popc(m1[g] & lm);
            if (h1[g] && pos1 < NS) sidx[g][pos1] = base + 256 + t;
            cnt[g] += t0 + t1;   // uniform across block
        }
        sel ^= 1;
        if (cnt[0] >= NS && cnt[1] >= NS && cnt[2] >= NS && cnt[3] >= NS)
            break;
    }
    __syncthreads();       // sidx visible to all warps

    // ---- outputs: thread t handles center g = t>>6, slot s = t&63 ----
    {
        const int g = t >> 6;
        const int s = t & 63;
        const int p = (pb0 & 1023) + g;
        const int cn = cnt[g] < NS ? cnt[g] : NS;
        const int first = (cn > 0) ? sidx[g][0] : NN;
        const bool real = (s < cn);
        const int v = real ? sidx[g][s] : NN;
        const size_t o = (size_t)(pb0 + g) * NS;
        g_idx[o + s] = v;   // masked (pad -> NN)
        float* out_idx =
            out + (size_t)BB * 131 * PP * NS + (size_t)BB * 3 * PP * NS;
        out_idx[o + s] = (float)(real ? v : first);   // idx0 (pad -> first)

        // grouped_xyz + xyz_feature channels
        const float qgx = (g == 0) ? qx[0] : (g == 1) ? qx[1]
                          : (g == 2) ? qx[2] : qx[3];
        const float qgy = (g == 0) ? qy[0] : (g == 1) ? qy[1]
                          : (g == 2) ? qy[2] : qy[3];
        const float qgz = (g == 0) ? qz[0] : (g == 1) ? qz[1]
                          : (g == 2) ? qz[2] : qz[3];
        float* gx = out + (size_t)BB * 131 * PP * NS;
#pragma unroll
        for (int c = 0; c < 3; c++) {
            const float q = (c == 0) ? qgx : (c == 1) ? qgy : qgz;
            const float src = (v < NN) ? xb[v * 3 + c] : 1000000.0f;
            const float gv = __fadd_rn(src, -q);
            gx[(((size_t)b * 3 + c) * PP + p) * NS + s] = gv;
            const float xf = (gv > 100000.0f) ? 0.0f : gv;
            out[(((size_t)b * 131 + c) * PP + p) * NS + s] = xf / 0.2f;
        }
    }
}

// ---------------------------------------------------------------------------
// Kernel A (stream 0): blocks [0,512) = ball query for batches 0-1 (long,
// scheduled first per R6 finding); blocks [512, 8704) = full transpose.
// ---------------------------------------------------------------------------
__global__ void __launch_bounds__(256) prep_kernel(
    const float* __restrict__ f, const float* __restrict__ xyz,
    const float* __restrict__ new_xyz, float* __restrict__ out) {
    const int bi = blockIdx.x;
    if (bi < 512) {
        ball_query_4(bi * 4, xyz, new_xyz, out);   // centers [0, 2048)
    } else {
        // ---------------- transpose (B,C,N) -> (B,N,C) ----------------
        __shared__ float tile[32][33];
        const int t = threadIdx.x;
        const int tb = bi - 512;          // 0..8191
        const int b = tb >> 11;           // 2048 blocks per batch
        const int rem = tb & 2047;
        const int nBase = (rem >> 2) * 32;
        const int cBase = (rem & 3) * 32;
        const float* fb = f + (size_t)b * CC * NN;
        float* ob = g_ftrans + (size_t)b * NN * CC;
        const int tx = t & 31, ty = t >> 5;  // 32 x 8
#pragma unroll
        for (int i = 0; i < 32; i += 8)
            tile[ty + i][tx] = fb[(size_t)(cBase + ty + i) * NN + nBase + tx];
        __syncthreads();
#pragma unroll
        for (int i = 0; i < 32; i += 8)
            ob[(size_t)(nBase + ty + i) * CC + cBase + tx] = tile[tx][ty + i];
    }
}

// ---------------------------------------------------------------------------
// Kernel B (side stream): ball query for batches 2-3 (512 blocks).
// ---------------------------------------------------------------------------
__global__ void __launch_bounds__(256) query_kernel(
    const float* __restrict__ xyz, const float* __restrict__ new_xyz,
    float* __restrict__ out) {
    ball_query_4(2048 + blockIdx.x * 4, xyz, new_xyz, out);  // centers [2048,4096)
}

// ---------------------------------------------------------------------------
// Kernel 2: feature gather. Block per (chunk-of-64-channels, p, b_local).
// LDG.128 gather -> STS.128 swizzled [s][ch] tile -> LDS + STG.128 output.
// ---------------------------------------------------------------------------
__global__ void __launch_bounds__(256, 8) gather_kernel(
    float* __restrict__ out, const int b_base) {
    __shared__ float ftile[64 * 64];    // 16 KB, swizzled
    __shared__ int smidx[NS];

    const int chunk = blockIdx.x;       // 0 / 1
    const int p = blockIdx.y;
    const int b = b_base + blockIdx.z;
    const int t = threadIdx.x;
    const int warp = t >> 5;
    const int lane = t & 31;

    if (t < NS) smidx[t] = g_idx[((size_t)b * PP + p) * NS + t];
    __syncthreads();

    // Phase A: gather. Warp handles 2 s-rows per iter (16 lanes x float4 each).
    const float* fb = g_ftrans + (size_t)b * NN * CC + chunk * 64;
    const int c4 = lane & 15;           // 16B group within the row
#pragma unroll
    for (int i = 0; i < 4; i++) {
        const int row = warp * 8 + i * 2 + (lane >> 4);
        const int n = smidx[row];
        float4 v = make_float4(0.f, 0.f, 0.f, 0.f);
        if (n < NN) v = *(const float4*)&fb[(size_t)n * CC + c4 * 4];
        *(float4*)&ftile[row * 64 + ((c4 ^ (row & 15)) << 2)] = v;
    }
    __syncthreads();

    // Phase B: write 64 channels x 64 s, STG.128 along s.
    float* nfb = out + (((size_t)b * 131 + 3 + chunk * 64) * PP + p) * NS;
    const int ch = t >> 2;              // 0..63 (within chunk)
#pragma unroll
    for (int k = 0; k < 4; k++) {
        const int sg = (t & 3) + 4 * k; // 0..15 (group of 4 s)
        float4 v;
        v.x = ftile[taddr(4 * sg + 0, ch)];
        v.y = ftile[taddr(4 * sg + 1, ch)];
        v.z = ftile[taddr(4 * sg + 2, ch)];
        v.w = ftile[taddr(4 * sg + 3, ch)];
        *(float4*)&nfb[(size_t)ch * PP * NS + sg * 4] = v;
    }
}

// ---------------------------------------------------------------------------
// Launch: fork-join two-stream graph.
//   stream0: prep(transpose + query b01) -> gather b01 ----------\
//   side   :            \-> (e1) query b23 -> (e2) --------------+-> gather b23
// Stream/events are created on the first (non-captured) correctness call and
// reused; per-call work is identical and deterministic.
// ---------------------------------------------------------------------------
static cudaStream_t get_side_stream() {
    static cudaStream_t s = nullptr;
    if (!s) cudaStreamCreateWithFlags(&s, cudaStreamNonBlocking);
    return s;
}
static cudaEvent_t get_event(int which) {
    static cudaEvent_t e[2] = {nullptr, nullptr};
    if (!e[which]) cudaEventCreateWithFlags(&e[which], cudaEventDisableTiming);
    return e[which];
}

extern "C" void kernel_launch(void* const* d_in, const int* in_sizes, int n_in,
                              void* d_out, int out_size) {
    const float* xyz      = (const float*)d_in[0];  // (B, N, 3)
    const float* new_xyz  = (const float*)d_in[1];  // (B, P, 3)
    const float* features = (const float*)d_in[2];  // (B, C, N)
    float* out = (float*)d_out;

    cudaStream_t s2 = get_side_stream();
    cudaEvent_t e1 = get_event(0);
    cudaEvent_t e2 = get_event(1);

    // kA: queries b01 (first) + full transpose
    prep_kernel<<<512 + 8192, 256>>>(features, xyz, new_xyz, out);
    cudaEventRecord(e1, 0);

    // side stream: queries b23, concurrent with gather b01
    cudaStreamWaitEvent(s2, e1, 0);
    query_kernel<<<512, 256, 0, s2>>>(xyz, new_xyz, out);
    cudaEventRecord(e2, s2);

    // stream 0: gather b01 (needs kA only)
    gather_kernel<<<dim3(2, PP, 2), 256>>>(out, 0);

    // join, then gather b23
    cudaStreamWaitEvent(0, e2, 0);
    gather_kernel<<<dim3(2, PP, 2), 256>>>(out, 2);
}